// round 4
// baseline (speedup 1.0000x reference)
#include <cuda_runtime.h>
#include <cstdint>
#include <math.h>

#define HID   128
#define G4    512
#define OUTC  7
#define LEN   2048
#define BATCH 10
#define TPB   256

// Packed fp32x2 FMA (Blackwell): 2 fp32 FMAs per lane per issue.
#define FMA2(d,a,b,c) asm("fma.rn.f32x2 %0, %1, %2, %3;" : "=l"(d) : "l"(a), "l"(b), "l"(c))

__device__ __forceinline__ unsigned smem_u32(const void* p) {
    return (unsigned)__cvta_generic_to_shared(p);
}
__device__ __forceinline__ unsigned my_ctarank() {
    unsigned r; asm("mov.u32 %0, %%cluster_ctarank;" : "=r"(r)); return r;
}
__device__ __forceinline__ unsigned mapa_u32(unsigned a, unsigned r) {
    unsigned o; asm("mapa.shared::cluster.u32 %0, %1, %2;" : "=r"(o) : "r"(a), "r"(r)); return o;
}
#define CLUSTER_SYNC() do { \
    asm volatile("barrier.cluster.arrive.aligned;" ::: "memory"); \
    asm volatile("barrier.cluster.wait.aligned;"   ::: "memory"); \
} while (0)

// One cluster of 2 CTAs per batch element. CTA rank r owns gate rows
// [r*256, r*256+256). Each thread owns one gate row; its 128 W_hh weights live
// in 64 packed f32x2 registers. Per step: register-resident matvec, DSMEM gate
// exchange (double-buffered, one cluster.sync/step), LSTM cell computed
// redundantly in both CTAs, logits/argmax/log_softmax, index recurrence.
__global__ void __cluster_dims__(2,1,1) __launch_bounds__(TPB,1)
lstm_decode_kernel(const float* __restrict__ h0,      const float* __restrict__ c0,
                   const float* __restrict__ tgt_oh,  const unsigned* __restrict__ tf_mask,
                   const float* __restrict__ W_ih,    const float* __restrict__ W_hh,
                   const float* __restrict__ b_ih,    const float* __restrict__ b_hh,
                   const float* __restrict__ W_out,   const float* __restrict__ b_out,
                   float* __restrict__ out)
{
    __shared__ __align__(16) float h_sm[HID];
    __shared__ float c_sm[HID];
    __shared__ __align__(16) float gates_sm[2][G4];   // double-buffered full gate vector
    __shared__ float wih_sm[G4 * OUTC];
    __shared__ float wout_sm[OUTC * HID];
    __shared__ float bout_sm[OUTC];
    __shared__ float lsm[OUTC];
    __shared__ int   sidx;                            // current one-hot input index
    __shared__ short tfidx_sm[LEN];                   // teacher-forced idx, or -1

    const int      tid  = threadIdx.x;
    const unsigned rank = my_ctarank();
    const int      b    = blockIdx.x >> 1;
    const int      g    = (int)rank * 256 + tid;      // this thread's global gate row

    // --- one-time setup -----------------------------------------------------
    // W_hh row into 64 packed f32x2 registers
    unsigned long long w[64];
    const unsigned long long* wr = (const unsigned long long*)(W_hh + (size_t)g * HID);
    #pragma unroll
    for (int k = 0; k < 64; k++) w[k] = wr[k];
    const float bias = b_ih[g] + b_hh[g];

    for (int i = tid; i < G4 * OUTC; i += TPB) wih_sm[i]  = W_ih[i];
    for (int i = tid; i < OUTC * HID; i += TPB) wout_sm[i] = W_out[i];
    if (tid < OUTC) bout_sm[tid] = b_out[tid];
    if (tid < HID) { h_sm[tid] = h0[b * HID + tid]; c_sm[tid] = c0[b * HID + tid]; }
    if (tid == 0) sidx = OUTC - 1;                    // x0 = one-hot at OUT-1

    // Precompute teacher-forcing indices. tf_mask read as 32-bit nonzero test
    // (covers both int32 and float32 encodings). tgt one-hot is exact {0,1}.
    for (int t = tid; t < LEN; t += TPB) {
        short v = -1;
        if (tf_mask[t] != 0u) {
            v = 0;
            #pragma unroll
            for (int k = 0; k < OUTC; k++)
                if (tgt_oh[(t + 1) * OUTC + k] > 0.5f) v = (short)k;
        }
        tfidx_sm[t] = v;
    }
    __syncthreads();
    CLUSTER_SYNC();

    const unsigned peer = rank ^ 1u;

    // --- time loop ----------------------------------------------------------
    for (int t = 0; t < LEN; t++) {
        const int cur = sidx;

        // gates[g] = h . W_hh[g,:] + bias[g] + W_ih[g, cur]   (x is one-hot)
        unsigned long long a0 = 0ull, a1 = 0ull;
        #pragma unroll
        for (int q = 0; q < 32; q++) {
            ulonglong2 hv = *reinterpret_cast<const ulonglong2*>(&h_sm[4 * q]);
            FMA2(a0, w[2 * q],     hv.x, a0);
            FMA2(a1, w[2 * q + 1], hv.y, a1);
        }
        float2 f0 = *reinterpret_cast<float2*>(&a0);
        float2 f1 = *reinterpret_cast<float2*>(&a1);
        float gv = (f0.x + f0.y) + (f1.x + f1.y) + bias + wih_sm[g * OUTC + cur];

        // publish gate value locally and into the peer CTA's buffer (DSMEM)
        float* gb = gates_sm[t & 1];
        gb[g] = gv;
        unsigned raddr = mapa_u32(smem_u32(&gb[g]), peer);
        asm volatile("st.shared::cluster.f32 [%0], %1;" :: "r"(raddr), "f"(gv) : "memory");

        CLUSTER_SYNC();   // release remote stores, acts as CTA barrier too

        // LSTM cell update (both CTAs redundantly, deterministic)
        if (tid < HID) {
            float ig = gb[tid], fg = gb[HID + tid], gg = gb[2 * HID + tid], og = gb[3 * HID + tid];
            float c  = c_sm[tid];
            float si = 1.0f / (1.0f + expf(-ig));
            float sf = 1.0f / (1.0f + expf(-fg));
            float so = 1.0f / (1.0f + expf(-og));
            float c2 = sf * c + si * tanhf(gg);
            float h2 = so * tanhf(c2);
            c_sm[tid] = c2;
            h_sm[tid] = h2;
        }
        __syncthreads();

        // logits: warp k computes logit k (128-dot, shfl reduce)
        const int wk = tid >> 5, lane = tid & 31;
        if (wk < OUTC) {
            float p = 0.0f;
            #pragma unroll
            for (int q = 0; q < 4; q++) {
                int j = lane + 32 * q;
                p = fmaf(h_sm[j], wout_sm[wk * HID + j], p);
            }
            #pragma unroll
            for (int off = 16; off; off >>= 1) p += __shfl_xor_sync(0xffffffffu, p, off);
            if (lane == 0) lsm[wk] = p + bout_sm[wk];
        }
        __syncthreads();

        // argmax (first-max tie-break), log_softmax, next-input index
        if (tid < 32) {
            float lv = (tid < OUTC) ? lsm[tid] : -3.4e38f;
            float m = lv; int ai = (tid < OUTC) ? tid : 1000;
            #pragma unroll
            for (int off = 16; off; off >>= 1) {
                float om = __shfl_xor_sync(0xffffffffu, m, off);
                int   oi = __shfl_xor_sync(0xffffffffu, ai, off);
                if (om > m || (om == m && oi < ai)) { m = om; ai = oi; }
            }
            float e = (tid < OUTC) ? expf(lv - m) : 0.0f;
            float s = e;
            #pragma unroll
            for (int off = 16; off; off >>= 1) s += __shfl_xor_sync(0xffffffffu, s, off);
            if (tid < OUTC && rank == 0) {
                float lg = logf(s);
                out[((size_t)b * LEN + t) * OUTC + tid] = lv - m - lg;
            }
            if (tid == 0) {
                int tv = tfidx_sm[t];
                sidx = (tv >= 0) ? tv : ai;
            }
        }
        __syncthreads();
    }

    // final states: hT then cT, after log_probs block
    if (rank == 0 && tid < HID) {
        out[(size_t)BATCH * LEN * OUTC + b * HID + tid]               = h_sm[tid];
        out[(size_t)BATCH * LEN * OUTC + BATCH * HID + b * HID + tid] = c_sm[tid];
    }
}

extern "C" void kernel_launch(void* const* d_in, const int* in_sizes, int n_in,
                              void* d_out, int out_size)
{
    (void)in_sizes; (void)n_in; (void)out_size;
    lstm_decode_kernel<<<BATCH * 2, TPB>>>(
        (const float*)d_in[0], (const float*)d_in[1], (const float*)d_in[2],
        (const unsigned*)d_in[3], (const float*)d_in[4], (const float*)d_in[5],
        (const float*)d_in[6], (const float*)d_in[7], (const float*)d_in[8],
        (const float*)d_in[9], (float*)d_out);
}

// round 6
// speedup vs baseline: 1.0817x; 1.0817x over previous
#include <cuda_runtime.h>
#include <cstdint>
#include <math.h>

#define HID   128
#define G4    512
#define OUTC  7
#define LEN   2048
#define BATCH 10
#define TPB   288   // 8 matvec warps (256 gate rows) + 1 control warp

// Packed fp32x2 FMA (Blackwell): 2 fp32 FMAs per lane per issue.
#define FMA2(d,a,b,c) asm("fma.rn.f32x2 %0, %1, %2, %3;" : "=l"(d) : "l"(a), "l"(b), "l"(c))

__device__ __forceinline__ unsigned smem_u32(const void* p) {
    return (unsigned)__cvta_generic_to_shared(p);
}
__device__ __forceinline__ unsigned my_ctarank() {
    unsigned r; asm("mov.u32 %0, %%cluster_ctarank;" : "=r"(r)); return r;
}
__device__ __forceinline__ unsigned mapa_u32(unsigned a, unsigned r) {
    unsigned o; asm("mapa.shared::cluster.u32 %0, %1, %2;" : "=r"(o) : "r"(a), "r"(r)); return o;
}
#define CLUSTER_SYNC() do { \
    asm volatile("barrier.cluster.arrive.aligned;" ::: "memory"); \
    asm volatile("barrier.cluster.wait.aligned;"   ::: "memory"); \
} while (0)

// 2-CTA cluster per batch element, partitioned by UNIT (not by gate):
// CTA r owns units [64r,64r+64) across all 4 gates => cell update is local.
// Cross-CTA per step: 64 h2 values + 14 logit partials + 64 release-adds on a
// monotonic flag counter (replaces barrier.cluster). Control warp (warp 8)
// overlaps argmax/log_softmax of step t-1 with step t's matvec dot.
__global__ void __cluster_dims__(2,1,1) __launch_bounds__(TPB, 1)
lstm_decode_kernel(const float* __restrict__ h0,      const float* __restrict__ c0,
                   const float* __restrict__ tgt_oh,  const unsigned* __restrict__ tf_mask,
                   const float* __restrict__ W_ih,    const float* __restrict__ W_hh,
                   const float* __restrict__ b_ih,    const float* __restrict__ b_hh,
                   const float* __restrict__ W_out,   const float* __restrict__ b_out,
                   float* __restrict__ out)
{
    __shared__ __align__(16) float h_sm[2][HID];     // double-buffered h
    __shared__ float c_sm[HID];                      // own half maintained
    __shared__ __align__(16) float act_sm[256];      // activated gates (local rows)
    __shared__ float wih_t[OUTC * G4];               // W_ih transposed [c][row]
    __shared__ float wout_sm[OUTC * HID];
    __shared__ float bout_sm[OUTC];
    __shared__ float part_sm[2][4][OUTC];            // double-buffered logit partials
    __shared__ int   sidx;
    __shared__ unsigned flag;                        // monotonic arrival counter
    __shared__ short tfidx_sm[LEN];

    const int      tid  = threadIdx.x;
    const unsigned rank = my_ctarank();
    const unsigned peer = rank ^ 1u;
    const int      b    = blockIdx.x >> 1;
    const bool     mv   = tid < 256;
    const int      qg   = tid >> 6;                      // gate type 0..3
    const int      u    = (int)rank * 64 + (tid & 63);   // owned unit
    const int      row  = qg * 128 + u;                  // owned gate row

    // --- one-time setup -----------------------------------------------------
    unsigned long long w[64];                            // 128 weights packed f32x2
    float bias = 0.0f;
    if (mv) {
        const unsigned long long* wr = (const unsigned long long*)(W_hh + (size_t)row * HID);
        #pragma unroll
        for (int k = 0; k < 64; k++) w[k] = wr[k];
        bias = b_ih[row] + b_hh[row];
    }
    for (int i = tid; i < OUTC * G4; i += TPB) {         // transpose W_ih
        int c = i >> 9, r0 = i & 511;
        wih_t[i] = W_ih[r0 * OUTC + c];
    }
    for (int i = tid; i < OUTC * HID; i += TPB) wout_sm[i] = W_out[i];
    if (tid < OUTC) bout_sm[tid] = b_out[tid];
    if (tid < HID) { h_sm[0][tid] = h0[b * HID + tid]; c_sm[tid] = c0[b * HID + tid]; }
    if (tid == 0) { sidx = OUTC - 1; flag = 0u; }
    for (int t = tid; t < LEN; t += TPB) {               // teacher-forcing indices
        short v = -1;
        if (tf_mask[t] != 0u) {
            v = 0;
            #pragma unroll
            for (int k = 0; k < OUTC; k++)
                if (tgt_oh[(t + 1) * OUTC + k] > 0.5f) v = (short)k;
        }
        tfidx_sm[t] = v;
    }
    __syncthreads();
    CLUSTER_SYNC();   // flag/smem init visible cluster-wide before any remote op

    const unsigned flag_l = smem_u32(&flag);
    const unsigned flag_r = mapa_u32(flag_l, peer);
    const unsigned h_r0   = mapa_u32(smem_u32(&h_sm[0][0]), peer);
    const unsigned part_r = mapa_u32(smem_u32(&part_sm[0][0][0]), peer);

    // --- time loop: iteration t does matvec/cell of step t and control of t-1
    for (int t = 0; t <= LEN; t++) {
        // wait for peer's step t-1 exchange (64 release-adds per step)
        if (t > 0) {
            const unsigned target = (unsigned)t * 64u;
            unsigned v;
            do {
                asm volatile("ld.acquire.cluster.shared::cta.u32 %0, [%1];"
                             : "=r"(v) : "r"(flag_l));
            } while (v < target);
        }

        // Phase A (concurrent): matvec dot (needs only h) || control for t-1
        float p = 0.0f;
        const float* hb = h_sm[t & 1];
        if (mv && t < LEN) {
            unsigned long long a0 = 0ull, a1 = 0ull;
            #pragma unroll
            for (int q = 0; q < 32; q++) {
                ulonglong2 hv = *reinterpret_cast<const ulonglong2*>(hb + 4 * q);
                FMA2(a0, w[2 * q],     hv.x, a0);
                FMA2(a1, w[2 * q + 1], hv.y, a1);
            }
            float2 f0 = *reinterpret_cast<float2*>(&a0);
            float2 f1 = *reinterpret_cast<float2*>(&a1);
            p = (f0.x + f0.y) + (f1.x + f1.y);
        }
        if (!mv && t > 0) {                              // control warp: step t-1
            const int lane = tid & 31;
            const int t1 = (t - 1) & 1;
            float lv = -3.4e38f;
            if (lane < OUTC)
                lv = ((part_sm[t1][0][lane] + part_sm[t1][1][lane])
                      + part_sm[t1][2][lane]) + part_sm[t1][3][lane] + bout_sm[lane];
            float m = lv; int ai = (lane < OUTC) ? lane : 1000;
            #pragma unroll
            for (int off = 16; off; off >>= 1) {
                float om = __shfl_xor_sync(0xffffffffu, m, off);
                int   oi = __shfl_xor_sync(0xffffffffu, ai, off);
                if (om > m || (om == m && oi < ai)) { m = om; ai = oi; }
            }
            float e = (lane < OUTC) ? expf(lv - m) : 0.0f;
            float s = e;
            #pragma unroll
            for (int off = 16; off; off >>= 1) s += __shfl_xor_sync(0xffffffffu, s, off);
            if (lane < OUTC && rank == 0) {
                float lg = logf(s);
                out[((size_t)b * LEN + (t - 1)) * OUTC + lane] = lv - m - lg;
            }
            if (lane == 0) {                             // both CTAs: identical sidx
                int tv = tfidx_sm[t - 1];
                sidx = (tv >= 0) ? tv : ai;
            }
        }
        __syncthreads();   // sidx ready

        // Phase B: finish gate value + activate (1 transcendental per thread)
        if (mv && t < LEN) {
            const int cur = sidx;
            float gv = p + bias + wih_t[cur * G4 + row];
            act_sm[tid] = (qg == 2) ? tanhf(gv) : (1.0f / (1.0f + expf(-gv)));
        }
        __syncthreads();

        // Phase C: local cell update + tiny cross-CTA exchange
        if (t < LEN && tid < 64) {
            const int uu = (int)rank * 64 + tid;
            float aI = act_sm[tid],       aF = act_sm[64 + tid];
            float aG = act_sm[128 + tid], aO = act_sm[192 + tid];
            float c  = c_sm[uu];
            float c2 = aF * c + aI * aG;
            float h2 = aO * tanhf(c2);
            c_sm[uu] = c2;
            h_sm[(t + 1) & 1][uu] = h2;
            unsigned hr = h_r0 + (unsigned)((((t + 1) & 1) * HID + uu) * 4);
            asm volatile("st.shared::cluster.f32 [%0], %1;" :: "r"(hr), "f"(h2) : "memory");

            float pk[OUTC];
            #pragma unroll
            for (int k = 0; k < OUTC; k++) pk[k] = h2 * wout_sm[k * HID + uu];
            #pragma unroll
            for (int k = 0; k < OUTC; k++) {
                #pragma unroll
                for (int off = 16; off; off >>= 1)
                    pk[k] += __shfl_xor_sync(0xffffffffu, pk[k], off);
            }
            if ((tid & 31) == 0) {
                int s4 = (int)rank * 2 + (tid >> 5);
                #pragma unroll
                for (int k = 0; k < OUTC; k++) {
                    part_sm[t & 1][s4][k] = pk[k];
                    unsigned pr = part_r + (unsigned)((((t & 1) * 4 + s4) * OUTC + k) * 4);
                    asm volatile("st.shared::cluster.f32 [%0], %1;" :: "r"(pr), "f"(pk[k]) : "memory");
                }
            }
            // release this thread's remote stores + count arrival on peer flag
            asm volatile("red.release.cluster.shared::cluster.add.u32 [%0], %1;"
                         :: "r"(flag_r), "r"(1u) : "memory");
        }
        __syncthreads();
    }

    // final states: each CTA writes its own 64 units of hT and cT
    if (tid < 64) {
        const int uu = (int)rank * 64 + tid;
        out[(size_t)BATCH * LEN * OUTC + b * HID + uu]               = h_sm[LEN & 1][uu];
        out[(size_t)BATCH * LEN * OUTC + BATCH * HID + b * HID + uu] = c_sm[uu];
    }
    CLUSTER_SYNC();   // keep smem alive until peer's last remote ops land
}

extern "C" void kernel_launch(void* const* d_in, const int* in_sizes, int n_in,
                              void* d_out, int out_size)
{
    (void)in_sizes; (void)n_in; (void)out_size;
    lstm_decode_kernel<<<BATCH * 2, TPB>>>(
        (const float*)d_in[0], (const float*)d_in[1], (const float*)d_in[2],
        (const unsigned*)d_in[3], (const float*)d_in[4], (const float*)d_in[5],
        (const float*)d_in[6], (const float*)d_in[7], (const float*)d_in[8],
        (const float*)d_in[9], (float*)d_out);
}